// round 16
// baseline (speedup 1.0000x reference)
#include <cuda_runtime.h>
#include <math.h>

#define BB 32768
#define NQUAD 8192
#define NN 27
#define HID 128
#define SINK_ITERS 20
#define NCHUNK 4
#define QCHUNK (NQUAD / NCHUNK)

__device__ float g_scores[(size_t)BB * NN * NN];

#define OFF_W2  0
#define OFF_W1  16384
#define OFF_B1  16896
#define OFF_B2  17024
#define OFF_LN1 17152
#define OFF_M   17160
#define OFF_CK  17268
#define OFF_SK  17300
#define OFF_BPK 17332
#define OFF_WPT 17364
#define OFF_BAT 20928
#define SB_A   0
#define SB_SR  0
#define SB_X   3584
#define SB_SRT 3696
#define SB_SSC 7536
#define SLAB   8320
#define SMEM_FLOATS (OFF_BAT + 4 * SLAB)
#define SMEM_BYTES  (SMEM_FLOATS * 4)

#define FFMA2ACC(d,a,b) asm("fma.rn.f32x2 %0, %1, %2, %0;" : "+l"(d) : "l"(a), "l"(b))
#define PADD(d,a,b)     asm("add.rn.f32x2 %0, %1, %2;" : "=l"(d) : "l"(a), "l"(b))

__device__ __forceinline__ unsigned long long dup2(float x) {
    unsigned long long r;
    asm("mov.b64 %0, {%1, %2};" : "=l"(r) : "f"(x), "f"(x));
    return r;
}
__device__ __forceinline__ float2 unpk(unsigned long long v) {
    float2 f;
    asm("mov.b64 {%0, %1}, %2;" : "=f"(f.x), "=f"(f.y) : "l"(v));
    return f;
}

__global__ void __launch_bounds__(256, 1)
k1_scores(const float* __restrict__ A, const float* __restrict__ m_,
          const float* __restrict__ ln1_g, const float* __restrict__ ln1_b,
          const float* __restrict__ W1, const float* __restrict__ b1,
          const float* __restrict__ W2, const float* __restrict__ b2,
          const float* __restrict__ ln2_g, const float* __restrict__ ln2_b,
          const float* __restrict__ protos, int qlo, int qhi)
{
    extern __shared__ float sm[];
    const int tid  = threadIdx.x;
    const int lane = tid & 31;
    const int q    = tid >> 6;
    const int htid = tid & 63;
    const int w2   = (tid >> 5) & 1;
    const int base = w2 * 14;

    for (int i = tid; i < HID * HID; i += 256) sm[OFF_W2 + i] = W2[i];
    for (int i = tid; i < 4 * HID; i += 256)   sm[OFF_W1 + i] = W1[i];
    if (tid < HID) {
        sm[OFF_B1 + tid] = b1[tid];
        sm[OFF_B2 + tid] = b2[tid];
        sm[OFF_BAT + 4000 + tid] = ln2_g[tid];
        sm[OFF_BAT + 4128 + tid] = ln2_b[tid];
    }
    if (tid < 4) { sm[OFF_LN1 + tid] = ln1_g[tid]; sm[OFF_LN1 + 4 + tid] = ln1_b[tid]; }
    __syncthreads();

    for (int idx = tid; idx < NN * HID; idx += 256) {
        int k = idx >> 7, j = idx & 127;
        sm[OFF_BAT + k * 129 + j] = protos[idx] * sm[OFF_BAT + 4000 + j];
    }
    __syncthreads();
    for (int idx = tid; idx < NN * HID; idx += 256) {
        int k = idx % NN, i = idx / NN;
        float acc = 0.f;
        const float* w2r = sm + OFF_W2 + i * HID;
        const float* pgr = sm + OFF_BAT + k * 129;
        for (int j = 0; j < HID; j++) acc = fmaf(w2r[j], pgr[j], acc);
        sm[OFF_WPT + k * 132 + i] = acc;
    }
    if (tid < NN) {
        float S = 0.f, c = 0.f, bp = 0.f;
        const float* pgr = sm + OFF_BAT + tid * 129;
        for (int j = 0; j < HID; j++) {
            float p = pgr[j];
            S += p;
            c = fmaf(sm[OFF_B2 + j], p, c);
            bp = fmaf(sm[OFF_BAT + 4128 + j], protos[tid * HID + j], bp);
        }
        sm[OFF_SK + tid] = S; sm[OFF_CK + tid] = c; sm[OFF_BPK + tid] = bp;
    }
    __syncthreads();
    if (tid < 16) sm[OFF_BAT + (tid >> 2) * SLAB + SB_X + NN * 4 + (tid & 3)] = 0.f;
    __syncthreads();

    int jj[12], oo[12];
#pragma unroll
    for (int u = 0; u < 12; u++) {
        int idx = tid + 256 * u;
        jj[u] = idx / (NN * NN);
        oo[u] = idx - jj[u] * (NN * NN);
    }
    float pf[12]; float mreg = 0.f;
    int bq = qlo + blockIdx.x;
    if (bq < qhi) {
        const float* src = A + (size_t)bq * (4 * NN * NN);
#pragma unroll
        for (int u = 0; u < 12; u++) {
            int idx = tid + 256 * u;
            pf[u] = (idx < 4 * NN * NN) ? src[idx] : 0.f;
        }
        if (tid < 4 * NN) mreg = m_[(size_t)bq * 4 * NN + tid];
    }

    for (; bq < qhi; bq += (int)gridDim.x) {
#pragma unroll
        for (int u = 0; u < 12; u++) {
            int idx = tid + 256 * u;
            if (idx < 4 * NN * NN)
                sm[OFF_BAT + jj[u] * SLAB + SB_A + oo[u]] = pf[u];
        }
        if (tid < 4 * NN) sm[OFF_M + tid] = mreg;
        __syncthreads();

        {
            int bqn = bq + (int)gridDim.x;
            if (bqn < qhi) {
                const float* src = A + (size_t)bqn * (4 * NN * NN);
#pragma unroll
                for (int u = 0; u < 12; u++) {
                    int idx = tid + 256 * u;
                    pf[u] = (idx < 4 * NN * NN) ? src[idx] : 0.f;
                }
                if (tid < 4 * NN) mreg = m_[(size_t)bqn * 4 * NN + tid];
            }
        }

        float* slab = sm + OFF_BAT + q * SLAB;

        if (tid < 4 * NN) {
            const int qq = tid / NN, n = tid - qq * NN;
            const float* sA = sm + OFF_BAT + qq * SLAB + SB_A + n * NN;
            float s = 0.f, t1 = 0.f, t2 = 0.f;
#pragma unroll
            for (int j = 0; j < NN; j++) {
                float a = sA[j];
                s += a;
                float v = (j == n) ? 0.f : a;
                if (v > t1) { t2 = t1; t1 = v; } else if (v > t2) t2 = v;
            }
            float f0 = log1pf(s), f3 = sm[OFF_M + tid];
            float mu = 0.25f * (f0 + t1 + t2 + f3);
            float d0 = f0 - mu, d1 = t1 - mu, d2 = t2 - mu, d3 = f3 - mu;
            float rs = rsqrtf(0.25f * (d0*d0 + d1*d1 + d2*d2 + d3*d3) + 1e-5f);
            float* x = sm + OFF_BAT + qq * SLAB + SB_X + n * 4;
            x[0] = d0 * rs * sm[OFF_LN1 + 0] + sm[OFF_LN1 + 4];
            x[1] = d1 * rs * sm[OFF_LN1 + 1] + sm[OFF_LN1 + 5];
            x[2] = d2 * rs * sm[OFF_LN1 + 2] + sm[OFF_LN1 + 6];
            x[3] = d3 * rs * sm[OFF_LN1 + 3] + sm[OFF_LN1 + 7];
        }
        __syncthreads();

        {
            const int n = htid & 31, ib = htid >> 5;
            if (n < 28) {
                const float* x = slab + SB_X + n * 4;
                float x0 = x[0], x1 = x[1], x2 = x[2], x3 = x[3];
#pragma unroll 1
                for (int it = 0; it < 16; it++) {
                    int i0 = ib * 64 + 4 * ((it + n) & 15);
                    float4 wa = *(const float4*)(sm + OFF_W1 + 0 * HID + i0);
                    float4 wb = *(const float4*)(sm + OFF_W1 + 1 * HID + i0);
                    float4 wc = *(const float4*)(sm + OFF_W1 + 2 * HID + i0);
                    float4 wd = *(const float4*)(sm + OFF_W1 + 3 * HID + i0);
                    float4 bb = *(const float4*)(sm + OFF_B1 + i0);
                    float4 r;
                    r.x = fmaxf(bb.x + x0*wa.x + x1*wb.x + x2*wc.x + x3*wd.x, 0.f);
                    r.y = fmaxf(bb.y + x0*wa.y + x1*wb.y + x2*wc.y + x3*wd.y, 0.f);
                    r.z = fmaxf(bb.z + x0*wa.z + x1*wb.z + x2*wc.z + x3*wd.z, 0.f);
                    r.w = fmaxf(bb.w + x0*wa.w + x1*wb.w + x2*wc.w + x3*wd.w, 0.f);
                    *(float4*)(slab + SB_SR + n * HID + i0) = r;
                    slab[SB_SRT + (i0 + 0) * 30 + n] = r.x;
                    slab[SB_SRT + (i0 + 1) * 30 + n] = r.y;
                    slab[SB_SRT + (i0 + 2) * 30 + n] = r.z;
                    slab[SB_SRT + (i0 + 3) * 30 + n] = r.w;
                }
            }
        }
        __syncthreads();

        float mu[14], rs[14];
        {
            unsigned long long acc[7][4];
#pragma unroll
            for (int t = 0; t < 7; t++)
#pragma unroll
                for (int c = 0; c < 4; c++) acc[t][c] = 0ull;
            const float* srt = slab + SB_SRT + base;
#pragma unroll 4
            for (int i = 0; i < HID; i++) {
                float4 w = *(const float4*)(sm + OFF_W2 + i * HID + 4 * lane);
                unsigned long long wd0 = dup2(w.x), wd1 = dup2(w.y);
                unsigned long long wd2 = dup2(w.z), wd3 = dup2(w.w);
#pragma unroll
                for (int t = 0; t < 7; t++) {
                    unsigned long long rp = *(const unsigned long long*)(srt + i * 30 + 2 * t);
                    FFMA2ACC(acc[t][0], rp, wd0);
                    FFMA2ACC(acc[t][1], rp, wd1);
                    FFMA2ACC(acc[t][2], rp, wd2);
                    FFMA2ACC(acc[t][3], rp, wd3);
                }
            }
            float s[14], s2[14];
#pragma unroll
            for (int r = 0; r < 14; r++) { s[r] = 0.f; s2[r] = 0.f; }
            unsigned long long bd[4];
#pragma unroll
            for (int c = 0; c < 4; c++) bd[c] = dup2(sm[OFF_B2 + 4 * lane + c]);
#pragma unroll
            for (int t = 0; t < 7; t++)
#pragma unroll
                for (int c = 0; c < 4; c++) {
                    unsigned long long v;
                    PADD(v, acc[t][c], bd[c]);
                    float2 f = unpk(v);
                    s[2*t]   += f.x;  s2[2*t]   = fmaf(f.x, f.x, s2[2*t]);
                    s[2*t+1] += f.y;  s2[2*t+1] = fmaf(f.y, f.y, s2[2*t+1]);
                }
#pragma unroll
            for (int r = 0; r < 14; r++) {
                float a = s[r], b = s2[r];
#pragma unroll
                for (int off = 16; off >= 1; off >>= 1) {
                    a += __shfl_xor_sync(0xffffffffu, a, off);
                    b += __shfl_xor_sync(0xffffffffu, b, off);
                }
                float m = a * (1.f / 128.f);
                mu[r] = m;
                rs[r] = rsqrtf(b * (1.f / 128.f) - m * m + 1e-5f);
            }
        }

        {
            const int kk = (lane < NN) ? lane : (NN - 1);
            const float ckv = sm[OFF_CK + kk];
            const float skv = sm[OFF_SK + kk];
            const float bpv = sm[OFF_BPK + kk];
            const ulonglong2* Wv = (const ulonglong2*)(sm + OFF_WPT);
            const float* srr = slab + SB_SR + base * HID;
            unsigned long long a5[14];
#pragma unroll
            for (int n = 0; n < 14; n++) a5[n] = 0ull;
#pragma unroll 1
            for (int jq = 0; jq < 32; jq++) {
                ulonglong2 wv = Wv[kk * 33 + jq];
#pragma unroll
                for (int n = 0; n < 14; n++) {
                    ulonglong2 hv = *(const ulonglong2*)(srr + n * HID + 4 * jq);
                    FFMA2ACC(a5[n], hv.x, wv.x);
                    FFMA2ACC(a5[n], hv.y, wv.y);
                }
            }
            if (lane < NN) {
#pragma unroll
                for (int n = 0; n < 14; n++) {
                    if (base + n < NN) {
                        float2 f = unpk(a5[n]);
                        float dot = f.x + f.y;
                        float sc = rs[n] * (dot + ckv - mu[n] * skv) + bpv;
                        slab[SB_SSC + lane * 29 + base + n] = sc;
                    }
                }
            }
        }
        __syncthreads();

        {
            float* dst = g_scores + (size_t)(4 * bq) * (NN * NN);
            for (int i = tid; i < 4 * NN * NN; i += 256) {
                int qq = i / (NN * NN), rem = i - qq * (NN * NN);
                int k = rem / NN, n = rem - k * NN;
                dst[i] = sm[OFF_BAT + qq * SLAB + SB_SSC + k * 29 + n];
            }
        }
        __syncthreads();
    }
}

__global__ void __launch_bounds__(256)
k2_sinkhorn(const float* __restrict__ tau_r, float* __restrict__ out, int b0, int bhi)
{
    const int warp = threadIdx.x >> 5;
    const int lane = threadIdx.x & 31;
    const int b = b0 + blockIdx.x * 8 + warp;
    if (b >= bhi) return;

    const float inv_tau = 1.0f / tau_r[0];
    const float* src = g_scores + (size_t)b * (NN * NN);

    float p[NN];
#pragma unroll
    for (int k = 0; k < NN; k++) {
        float v = (lane < NN) ? src[k * NN + lane] : 0.f;
        p[k] = (lane < NN) ? __expf(v * inv_tau) : 0.f;
    }
#pragma unroll 1
    for (int it = 0; it < SINK_ITERS; it++) {
#pragma unroll
        for (int k = 0; k < NN; k++) {
            float s = p[k];
            s += __shfl_xor_sync(0xffffffffu, s, 16);
            s += __shfl_xor_sync(0xffffffffu, s, 8);
            s += __shfl_xor_sync(0xffffffffu, s, 4);
            s += __shfl_xor_sync(0xffffffffu, s, 2);
            s += __shfl_xor_sync(0xffffffffu, s, 1);
            p[k] *= __fdividef(1.f, s);
        }
        float c = 0.f;
#pragma unroll
        for (int k = 0; k < NN; k++) c += p[k];
        float ci = (lane < NN) ? __fdividef(1.f, c) : 0.f;
#pragma unroll
        for (int k = 0; k < NN; k++) p[k] *= ci;
    }
    float* dst = out + (size_t)b * (NN * NN);
    if (lane < NN) {
#pragma unroll
        for (int k = 0; k < NN; k++) dst[k * NN + lane] = p[k];
    }
}

extern "C" void kernel_launch(void* const* d_in, const int* in_sizes, int n_in,
                              void* d_out, int out_size)
{
    const float* A      = (const float*)d_in[0];
    const float* m_     = (const float*)d_in[1];
    const float* tau_r  = (const float*)d_in[2];
    const float* ln1_g  = (const float*)d_in[3];
    const float* ln1_b  = (const float*)d_in[4];
    const float* W1     = (const float*)d_in[5];
    const float* b1     = (const float*)d_in[6];
    const float* W2     = (const float*)d_in[7];
    const float* b2     = (const float*)d_in[8];
    const float* ln2_g  = (const float*)d_in[9];
    const float* ln2_b  = (const float*)d_in[10];
    const float* protos = (const float*)d_in[11];

    static cudaStream_t s2 = nullptr;
    static cudaEvent_t evF[NCHUNK];
    static cudaEvent_t evJ = nullptr;
    if (s2 == nullptr) {
        cudaStreamCreateWithFlags(&s2, cudaStreamNonBlocking);
        for (int c = 0; c < NCHUNK; c++)
            cudaEventCreateWithFlags(&evF[c], cudaEventDisableTiming);
        cudaEventCreateWithFlags(&evJ, cudaEventDisableTiming);
    }

    int smCount = 148;
    cudaDeviceGetAttribute(&smCount, cudaDevAttrMultiProcessorCount, 0);
    cudaFuncSetAttribute((const void*)k1_scores,
                         cudaFuncAttributeMaxDynamicSharedMemorySize, SMEM_BYTES);

    for (int c = 0; c < NCHUNK; c++) {
        int qlo = c * QCHUNK, qhi = qlo + QCHUNK;
        k1_scores<<<smCount, 256, SMEM_BYTES>>>(A, m_, ln1_g, ln1_b, W1, b1,
                                                W2, b2, ln2_g, ln2_b, protos,
                                                qlo, qhi);
        cudaEventRecord(evF[c], 0);
        cudaStreamWaitEvent(s2, evF[c], 0);
        int b0 = qlo * 4, bn = QCHUNK * 4;
        k2_sinkhorn<<<(bn + 7) / 8, 256, 0, s2>>>(tau_r, (float*)d_out, b0, b0 + bn);
    }
    cudaEventRecord(evJ, s2);
    cudaStreamWaitEvent(0, evJ, 0);
}